// round 10
// baseline (speedup 1.0000x reference)
#include <cuda_runtime.h>
#include <cstdint>
#include <math.h>

#define BATCH 8192
#define UNITS 1024
#define T_STEPS 30
#define AR 12
#define RRES 64
#define GDIM 3072   // 3*UNITS

// ---------------- device scratch (static, no allocations) ----------------
__device__ float g_h[2][(size_t)BATCH * UNITS];      // ping-pong hidden state
__device__ float g_A[77 * GDIM];                     // [W_enc; b_enc] @ W_gru
__device__ float g_logits[(size_t)BATCH * 76];       // [ang(12) | rad(64)] + bias
__device__ int   g_ia[BATCH];
__device__ int   g_ir[BATCH];

// ---------------- Threefry-2x32 (matches JAX exactly) ----------------
__host__ __device__ static inline uint32_t rotl32(uint32_t v, int d) {
    return (v << d) | (v >> (32 - d));
}

__host__ __device__ static inline void tf_round4(uint32_t& x0, uint32_t& x1,
                                                 int r0, int r1, int r2, int r3) {
    x0 += x1; x1 = rotl32(x1, r0); x1 ^= x0;
    x0 += x1; x1 = rotl32(x1, r1); x1 ^= x0;
    x0 += x1; x1 = rotl32(x1, r2); x1 ^= x0;
    x0 += x1; x1 = rotl32(x1, r3); x1 ^= x0;
}

__host__ __device__ static inline void tf2x32(uint32_t k0, uint32_t k1,
                                              uint32_t x0, uint32_t x1,
                                              uint32_t& o0, uint32_t& o1) {
    uint32_t ks2 = k0 ^ k1 ^ 0x1BD11BDAu;
    x0 += k0; x1 += k1;
    tf_round4(x0, x1, 13, 15, 26, 6);  x0 += k1;  x1 += ks2 + 1u;
    tf_round4(x0, x1, 17, 29, 16, 24); x0 += ks2; x1 += k0 + 2u;
    tf_round4(x0, x1, 13, 15, 26, 6);  x0 += k0;  x1 += k1 + 3u;
    tf_round4(x0, x1, 17, 29, 16, 24); x0 += k1;  x1 += ks2 + 4u;
    tf_round4(x0, x1, 13, 15, 26, 6);  x0 += ks2; x1 += k0 + 5u;
    o0 = x0; o1 = x1;
}

// JAX *partitionable* threefry random bits (jax_threefry_partitionable=True):
// element e of a flat array -> counter (hi=0, lo=e), bits = o0 ^ o1.
// Then uniform[tiny,1): max(bitcast(0x3F800000 | bits>>9) - 1, tiny); gumbel = -log(-log u).
__device__ static inline float jax_gumbel(uint32_t k0, uint32_t k1, uint32_t e) {
    uint32_t o0, o1;
    tf2x32(k0, k1, 0u, e, o0, o1);
    uint32_t bitsv = o0 ^ o1;
    float f = __uint_as_float(0x3F800000u | (bitsv >> 9)) - 1.0f;   // [0,1)
    float u = fmaxf(f, 1.17549435e-38f);                            // minval=tiny
    return -logf(-logf(u));
}

// ---------------- kernel 0: A = [W_enc; b_enc] @ W_gru ----------------
__global__ void precompA_kernel(const float* __restrict__ W_enc,
                                const float* __restrict__ b_enc,
                                const float* __restrict__ W_gru) {
    int r = blockIdx.y;                       // 0..76
    int c = blockIdx.x * 256 + threadIdx.x;   // 0..3071
    const float* e = (r < 76) ? (W_enc + (size_t)r * UNITS) : b_enc;
    float acc = 0.f;
    for (int k = 0; k < UNITS; k++)
        acc = fmaf(e[k], W_gru[(size_t)k * GDIM + c], acc);
    g_A[(size_t)r * GDIM + c] = acc;
}

// ---------------- kernel 1: fused GRU step (h @ U_gru + gate math) ----------------
// grid (UNITS/64, BATCH/64), 256 threads. Each thread: 4x4 outputs x 3 gates.
__global__ void __launch_bounds__(256) gru_kernel(int t, const float* __restrict__ s,
                                                  const float* __restrict__ Ug,
                                                  const float* __restrict__ bg) {
    const float* hin = (t == 0) ? s : g_h[(t - 1) & 1];
    float* hout = g_h[t & 1];

    __shared__ __align__(16) float shA[16][68];       // [k][row]
    __shared__ __align__(16) float shB[3][16][64];    // [gate][k][col]

    int tid = threadIdx.x;
    int tx = tid & 15, ty = tid >> 4;
    int row0 = blockIdx.y * 64;
    int col0 = blockIdx.x * 64;

    float acc[3][4][4];
#pragma unroll
    for (int g = 0; g < 3; g++)
#pragma unroll
        for (int i = 0; i < 4; i++)
#pragma unroll
            for (int j = 0; j < 4; j++) acc[g][i][j] = 0.f;

    int lr = tid >> 2, lk = (tid & 3) * 4;       // A-tile load coords
    int lc = tid & 63, lkr = tid >> 6;           // B-tile load coords

    for (int k0 = 0; k0 < UNITS; k0 += 16) {
        float4 av = *(const float4*)(hin + (size_t)(row0 + lr) * UNITS + k0 + lk);
        shA[lk + 0][lr] = av.x; shA[lk + 1][lr] = av.y;
        shA[lk + 2][lr] = av.z; shA[lk + 3][lr] = av.w;
#pragma unroll
        for (int g = 0; g < 3; g++) {
            const float* src = Ug + (size_t)k0 * GDIM + g * UNITS + col0 + lc;
#pragma unroll
            for (int j = 0; j < 4; j++)
                shB[g][lkr + j * 4][lc] = src[(size_t)(lkr + j * 4) * GDIM];
        }
        __syncthreads();
#pragma unroll
        for (int k = 0; k < 16; k++) {
            float4 a  = *(const float4*)&shA[k][ty * 4];
            float4 b0 = *(const float4*)&shB[0][k][tx * 4];
            float4 b1 = *(const float4*)&shB[1][k][tx * 4];
            float4 b2 = *(const float4*)&shB[2][k][tx * 4];
            float as[4] = {a.x, a.y, a.z, a.w};
            float bs[3][4] = {{b0.x, b0.y, b0.z, b0.w},
                              {b1.x, b1.y, b1.z, b1.w},
                              {b2.x, b2.y, b2.z, b2.w}};
#pragma unroll
            for (int i = 0; i < 4; i++)
#pragma unroll
                for (int g = 0; g < 3; g++)
#pragma unroll
                    for (int j = 0; j < 4; j++)
                        acc[g][i][j] = fmaf(as[i], bs[g][j], acc[g][i][j]);
        }
        __syncthreads();
    }

    // epilogue: gx gather + gate math + h update
#pragma unroll
    for (int i = 0; i < 4; i++) {
        int row = row0 + ty * 4 + i;
        int ia = 0, ir = 0;
        if (t > 0) { ia = g_ia[row]; ir = g_ir[row]; }
#pragma unroll
        for (int j = 0; j < 4; j++) {
            int cu = col0 + tx * 4 + j;
            float gx[3];
#pragma unroll
            for (int g = 0; g < 3; g++) {
                int c = g * UNITS + cu;
                float v = bg[c];
                if (t > 0)
                    v += g_A[(size_t)ia * GDIM + c]
                       + g_A[(size_t)(12 + ir) * GDIM + c]
                       + g_A[(size_t)76 * GDIM + c];
                gx[g] = v;
            }
            float z = 1.f / (1.f + expf(-(gx[0] + acc[0][i][j])));
            float r = 1.f / (1.f + expf(-(gx[1] + acc[1][i][j])));
            float n = tanhf(gx[2] + r * acc[2][i][j]);
            float hv = hin[(size_t)row * UNITS + cu];
            hout[(size_t)row * UNITS + cu] = z * hv + (1.f - z) * n;
        }
    }
}

// ---------------- kernel 2: logits = h @ [W_ang | W_rad] + bias ----------------
// grid BATCH/64, 256 threads. Thread owns (row = tid&63, 20 cols = (tid>>6)*20..)
__global__ void __launch_bounds__(256) logits_kernel(int t,
        const float* __restrict__ Wa, const float* __restrict__ Wr,
        const float* __restrict__ ba, const float* __restrict__ br) {
    const float* h = g_h[t & 1];
    __shared__ __align__(16) float shHT[64][65];   // [k][row]
    __shared__ __align__(16) float shW[64][80];    // [k][col padded]
    int tid = threadIdx.x;
    int row0 = blockIdx.x * 64;
    int rr = tid & 63, cg = tid >> 6;

    float acc[20];
#pragma unroll
    for (int i = 0; i < 20; i++) acc[i] = 0.f;

    for (int k0 = 0; k0 < UNITS; k0 += 64) {
        {
            int r = tid >> 2;
            int kq = (tid & 3) * 16;
            const float* src = h + (size_t)(row0 + r) * UNITS + k0 + kq;
#pragma unroll
            for (int j = 0; j < 4; j++) {
                float4 v = *(const float4*)(src + j * 4);
                shHT[kq + j * 4 + 0][r] = v.x;
                shHT[kq + j * 4 + 1][r] = v.y;
                shHT[kq + j * 4 + 2][r] = v.z;
                shHT[kq + j * 4 + 3][r] = v.w;
            }
        }
        for (int idx = tid; idx < 64 * 80; idx += 256) {
            int k = idx / 80, c = idx % 80;
            float v = 0.f;
            if (c < 12)      v = Wa[(size_t)(k0 + k) * AR + c];
            else if (c < 76) v = Wr[(size_t)(k0 + k) * RRES + (c - 12)];
            shW[k][c] = v;
        }
        __syncthreads();
#pragma unroll 8
        for (int k = 0; k < 64; k++) {
            float hv = shHT[k][rr];
#pragma unroll
            for (int q = 0; q < 5; q++) {
                float4 w = *(const float4*)&shW[k][cg * 20 + q * 4];
                acc[q * 4 + 0] = fmaf(hv, w.x, acc[q * 4 + 0]);
                acc[q * 4 + 1] = fmaf(hv, w.y, acc[q * 4 + 1]);
                acc[q * 4 + 2] = fmaf(hv, w.z, acc[q * 4 + 2]);
                acc[q * 4 + 3] = fmaf(hv, w.w, acc[q * 4 + 3]);
            }
        }
        __syncthreads();
    }
    int row = row0 + rr;
#pragma unroll
    for (int i = 0; i < 20; i++) {
        int c = cg * 20 + i;
        if (c < 76) {
            float b = (c < 12) ? ba[c] : br[c - 12];
            g_logits[(size_t)row * 76 + c] = acc[i] + b;
        }
    }
}

// ---------------- kernel 3: sampling + softmax + output writes ----------------
// one warp per row
__global__ void __launch_bounds__(128) sample_kernel(int t,
        unsigned ka0, unsigned ka1, unsigned kr0, unsigned kr1,
        float* __restrict__ out) {
    int row = blockIdx.x * 4 + (threadIdx.x >> 5);
    int lane = threadIdx.x & 31;
    const float* lg = &g_logits[(size_t)row * 76];
    const float NEG = -__int_as_float(0x7f800000);  // -inf

    // ---- angle head (12 categories, lanes 0..11) ----
    float la = NEG, ya = NEG;
    if (lane < AR) {
        la = lg[lane];
        ya = la + jax_gumbel(ka0, ka1, (unsigned)row * AR + lane);
    }
    float bv = ya; int bi = (lane < AR) ? lane : 1000;
#pragma unroll
    for (int off = 16; off; off >>= 1) {
        float ov = __shfl_xor_sync(0xffffffffu, bv, off);
        int   oi = __shfl_xor_sync(0xffffffffu, bi, off);
        if (ov > bv || (ov == bv && oi < bi)) { bv = ov; bi = oi; }
    }
    int aidx = bi;
    float m = la;
#pragma unroll
    for (int off = 16; off; off >>= 1) m = fmaxf(m, __shfl_xor_sync(0xffffffffu, m, off));
    float ex = (lane < AR) ? expf(la - m) : 0.f;
    float sm = ex;
#pragma unroll
    for (int off = 16; off; off >>= 1) sm += __shfl_xor_sync(0xffffffffu, sm, off);
    if (lane < AR) {
        size_t o = (size_t)row * (T_STEPS * AR) + (size_t)t * AR + lane;
        out[o] = (lane == aidx) ? 1.f : 0.f;
        out[(size_t)BATCH * T_STEPS * AR + o] = ex / sm;
    }

    // ---- radius head (64 categories, 2 per lane) ----
    float l0 = lg[AR + lane], l1 = lg[AR + 32 + lane];
    unsigned e0 = (unsigned)row * RRES + lane;
    float y0 = l0 + jax_gumbel(kr0, kr1, e0);
    float y1 = l1 + jax_gumbel(kr0, kr1, e0 + 32);
    float bv2; int bi2;
    if (y1 > y0) { bv2 = y1; bi2 = lane + 32; } else { bv2 = y0; bi2 = lane; }
#pragma unroll
    for (int off = 16; off; off >>= 1) {
        float ov = __shfl_xor_sync(0xffffffffu, bv2, off);
        int   oi = __shfl_xor_sync(0xffffffffu, bi2, off);
        if (ov > bv2 || (ov == bv2 && oi < bi2)) { bv2 = ov; bi2 = oi; }
    }
    int ridx = bi2;
    float m2 = fmaxf(l0, l1);
#pragma unroll
    for (int off = 16; off; off >>= 1) m2 = fmaxf(m2, __shfl_xor_sync(0xffffffffu, m2, off));
    float e0x = expf(l0 - m2), e1x = expf(l1 - m2);
    float s2 = e0x + e1x;
#pragma unroll
    for (int off = 16; off; off >>= 1) s2 += __shfl_xor_sync(0xffffffffu, s2, off);

    const size_t ROH = (size_t)BATCH * T_STEPS * AR * 2;
    const size_t RPR = ROH + (size_t)BATCH * T_STEPS * RRES;
    size_t ro = (size_t)row * (T_STEPS * RRES) + (size_t)t * RRES + lane;
    out[ROH + ro]      = (lane == ridx)      ? 1.f : 0.f;
    out[ROH + ro + 32] = (lane + 32 == ridx) ? 1.f : 0.f;
    out[RPR + ro]      = e0x / s2;
    out[RPR + ro + 32] = e1x / s2;

    if (lane == 0) { g_ia[row] = aidx; g_ir[row] = ridx; }
}

// ---------------- launcher ----------------
extern "C" void kernel_launch(void* const* d_in, const int* in_sizes, int n_in,
                              void* d_out, int out_size) {
    const float* s     = (const float*)d_in[0];
    const float* W_enc = (const float*)d_in[1];
    const float* b_enc = (const float*)d_in[2];
    const float* W_gru = (const float*)d_in[3];
    const float* U_gru = (const float*)d_in[4];
    const float* b_gru = (const float*)d_in[5];
    const float* W_ang = (const float*)d_in[6];
    const float* b_ang = (const float*)d_in[7];
    const float* W_rad = (const float*)d_in[8];
    const float* b_rad = (const float*)d_in[9];
    float* out = (float*)d_out;

    precompA_kernel<<<dim3(GDIM / 256, 77), 256>>>(W_enc, b_enc, W_gru);

    for (int t = 0; t < T_STEPS; t++) {
        // Partitionable (foldlike) split chain:
        //   step key[t]   = threefry(root=(0,42), counter (0, t))   [both words]
        //   (k_a, k_r)    = split(key_t, 2): child i = threefry(key_t, (0, i)) [both words]
        uint32_t kt0, kt1;
        tf2x32(0u, 42u, 0u, (uint32_t)t, kt0, kt1);
        uint32_t a0, a1, r0, r1;
        tf2x32(kt0, kt1, 0u, 0u, a0, a1);   // k_a
        tf2x32(kt0, kt1, 0u, 1u, r0, r1);   // k_r

        gru_kernel<<<dim3(UNITS / 64, BATCH / 64), 256>>>(t, s, U_gru, b_gru);
        logits_kernel<<<BATCH / 64, 256>>>(t, W_ang, W_rad, b_ang, b_rad);
        sample_kernel<<<BATCH / 4, 128>>>(t, a0, a1, r0, r1, out);
    }
}